// round 12
// baseline (speedup 1.0000x reference)
#include <cuda_runtime.h>
#include <cuda_bf16.h>
#include <cstdint>

#define GN 100000
#define GE 1600000
#define HEADS 4
#define ODIM 32
#define HO 128   /* HEADS*ODIM */
#define IND 128
#define NB 98    /* ceil(GN/1024) scan blocks */
#define LDT 136  /* padded bf16 row stride for smem tiles */

// ---------------- scratch (device globals; no allocation allowed) ----------
__device__ float  g_h[(size_t)GN * HO];          // projected features, 51.2 MB
__device__ float4 g_ssrc[GN];                    // per-node src scores (4 heads)
__device__ float4 g_sddn[2 * GN];                // [2n]=sdst, [2n+1]=denom (32B pair)
__device__ int    g_deg[GN];                     // in-degree histogram
__device__ int    g_incl[GN];                    // per-block inclusive scan
__device__ int    g_bsum[NB];                    // block sums
__device__ int    g_bpref[NB];                   // inclusive scan of block sums
__device__ int    g_rowoff[GN + 1];              // CSR row offsets (by dst)
__device__ int    g_cursor[GN];                  // scatter cursors
__device__ int2   g_csr[GE];                     // CSR: (src, log-weight bits)

// ---------------- helpers ----------------
__device__ __forceinline__ uint32_t smem_u32(const void* p) {
    uint32_t a;
    asm("{ .reg .u64 t; cvta.to.shared.u64 t, %1; cvt.u32.u64 %0, t; }"
        : "=r"(a) : "l"(p));
    return a;
}
__device__ __forceinline__ void ldsm4(uint32_t& r0, uint32_t& r1,
                                      uint32_t& r2, uint32_t& r3, uint32_t addr) {
    asm volatile("ldmatrix.sync.aligned.m8n8.x4.shared.b16 {%0,%1,%2,%3}, [%4];"
                 : "=r"(r0), "=r"(r1), "=r"(r2), "=r"(r3) : "r"(addr));
}
__device__ __forceinline__ void mma16816(float* c, uint32_t a0, uint32_t a1,
                                         uint32_t a2, uint32_t a3,
                                         uint32_t b0, uint32_t b1) {
    asm volatile("mma.sync.aligned.m16n8k16.row.col.f32.bf16.bf16.f32 "
                 "{%0,%1,%2,%3}, {%4,%5,%6,%7}, {%8,%9}, {%0,%1,%2,%3};"
                 : "+f"(c[0]), "+f"(c[1]), "+f"(c[2]), "+f"(c[3])
                 : "r"(a0), "r"(a1), "r"(a2), "r"(a3), "r"(b0), "r"(b1));
}
__device__ __forceinline__ void split2(float v, __nv_bfloat16& h, __nv_bfloat16& l) {
    h = __float2bfloat16(v);
    l = __float2bfloat16(v - __bfloat162float(h));
}
// pack a float2 into hi/lo bf16x2 fragments (elem0 in low half)
__device__ __forceinline__ void packHL(float2 f, uint32_t& h, uint32_t& l) {
    __nv_bfloat16 h0, h1, l0, l1;
    split2(f.x, h0, l0);
    split2(f.y, h1, l1);
    __nv_bfloat162 hh(h0, h1), ll(l0, l1);
    h = *(uint32_t*)&hh;
    l = *(uint32_t*)&ll;
}
__device__ __forceinline__ float lexp(float v) {
    v = (v >= 0.f) ? v : 0.2f * v;   // leaky_relu(0.2)
    return __expf(v);                // scores bounded; no max-shift needed
}

// ---------------- zero degree counters ----------------
__global__ void zero_deg_kernel() {
    int i = blockIdx.x * blockDim.x + threadIdx.x;
    if (i < GN) g_deg[i] = 0;
}

// ---------------- degree histogram over dst (2 edges/thread) --------------
__global__ void hist_kernel(const int* __restrict__ ei) {
    int i = blockIdx.x * blockDim.x + threadIdx.x;
    if (i >= GE / 2) return;
    int2 d2 = ((const int2*)(ei + GE))[i];
    atomicAdd(&g_deg[d2.x], 1);
    atomicAdd(&g_deg[d2.y], 1);
}

// ---------------- per-block inclusive scan ----------------
__global__ void __launch_bounds__(1024) scan1_kernel() {
    int i = blockIdx.x * 1024 + threadIdx.x;
    int v = (i < GN) ? g_deg[i] : 0;
    int lane = threadIdx.x & 31, w = threadIdx.x >> 5;
    int s = v;
#pragma unroll
    for (int o = 1; o < 32; o <<= 1) {
        int t = __shfl_up_sync(0xFFFFFFFFu, s, o);
        if (lane >= o) s += t;
    }
    __shared__ int ws[32];
    if (lane == 31) ws[w] = s;
    __syncthreads();
    if (w == 0) {
        int t = ws[lane];
#pragma unroll
        for (int o = 1; o < 32; o <<= 1) {
            int u = __shfl_up_sync(0xFFFFFFFFu, t, o);
            if (lane >= o) t += u;
        }
        ws[lane] = t;
    }
    __syncthreads();
    if (w > 0) s += ws[w - 1];
    if (i < GN) g_incl[i] = s;
    if (threadIdx.x == 1023) g_bsum[blockIdx.x] = s;
}

// ---- h = x @ W^T: mma.sync split-bf16, A-from-registers, W-only smem -----
// 256 thr / 8 warps / 64 rows per CTA; 2 CTAs per SM.
// warp tile: 16 rows x 64 cols (rg = wid>>1, ch = wid&1).
// passes fused: (Ah+Al)*Wh share B fragments, then Ah*Wl.
__global__ void __launch_bounds__(256, 2) gemm_mma_kernel(const float* __restrict__ x,
                                                          const float* __restrict__ W,
                                                          const float* __restrict__ a_src,
                                                          const float* __restrict__ a_dst) {
    extern __shared__ char smem[];
    __nv_bfloat16* sWh = (__nv_bfloat16*)smem;
    __nv_bfloat16* sWl = sWh + 128 * LDT;

    const int tid = threadIdx.x;
    const int wid = tid >> 5;
    const int lane = tid & 31;
    const int rg = wid >> 1;        // row group 0..3
    const int ch = wid & 1;         // col half 0..1
    const int rowBase = blockIdx.x * 64;

    // ---- A fragments from global, split hi/lo in registers ----
    uint32_t aH[32], aL[32];
    {
        const int g4 = lane >> 2, tig = lane & 3;
        int row0 = rowBase + rg * 16 + g4;
        int row1 = row0 + 8;
        bool v0 = row0 < GN, v1 = row1 < GN;
        const float* xr0 = x + (size_t)row0 * IND;
        const float* xr1 = x + (size_t)row1 * IND;
        const float2 z2 = make_float2(0.f, 0.f);
#pragma unroll
        for (int ks = 0; ks < 8; ks++) {
            int c0 = ks * 16 + tig * 2;
            int c1 = c0 + 8;
            float2 f0 = v0 ? *(const float2*)(xr0 + c0) : z2;
            float2 f1 = v1 ? *(const float2*)(xr1 + c0) : z2;
            float2 f2 = v0 ? *(const float2*)(xr0 + c1) : z2;
            float2 f3 = v1 ? *(const float2*)(xr1 + c1) : z2;
            packHL(f0, aH[ks * 4 + 0], aL[ks * 4 + 0]);
            packHL(f1, aH[ks * 4 + 1], aL[ks * 4 + 1]);
            packHL(f2, aH[ks * 4 + 2], aL[ks * 4 + 2]);
            packHL(f3, aH[ks * 4 + 3], aL[ks * 4 + 3]);
        }
    }

    // ---- W -> smem hi/lo (cooperative) ----
    for (int it = tid; it < 4096; it += 256) {
        int row = it >> 5;
        int col = (it & 31) * 4;
        float4 w = *(const float4*)(W + (size_t)row * IND + col);
        __nv_bfloat16 h0, h1, h2, h3, l0, l1, l2, l3;
        split2(w.x, h0, l0); split2(w.y, h1, l1);
        split2(w.z, h2, l2); split2(w.w, h3, l3);
        int o = row * LDT + col;
        *(__nv_bfloat162*)(sWh + o)     = __nv_bfloat162(h0, h1);
        *(__nv_bfloat162*)(sWh + o + 2) = __nv_bfloat162(h2, h3);
        *(__nv_bfloat162*)(sWl + o)     = __nv_bfloat162(l0, l1);
        *(__nv_bfloat162*)(sWl + o + 2) = __nv_bfloat162(l2, l3);
    }
    __syncthreads();

    float acc[32];
#pragma unroll
    for (int i = 0; i < 32; i++) acc[i] = 0.f;

    const int bRow = ch * 64 + (lane & 7) + ((lane >> 4) << 3);
    const int bKH  = ((lane >> 3) & 1) * 8;
    const uint32_t whBase = smem_u32(sWh) + (uint32_t)(bRow * LDT + bKH) * 2u;
    const uint32_t wlBase = smem_u32(sWl) + (uint32_t)(bRow * LDT + bKH) * 2u;

#pragma unroll
    for (int ks = 0; ks < 8; ks++) {
        const uint32_t* ah = aH + ks * 4;
        const uint32_t* al = aL + ks * 4;
#pragma unroll
        for (int tp = 0; tp < 4; tp++) {
            uint32_t b0, b1, b2, b3;
            ldsm4(b0, b1, b2, b3, whBase + (uint32_t)(tp * 16 * LDT) * 2u + ks * 32);
            mma16816(acc + (2 * tp) * 4,     ah[0], ah[1], ah[2], ah[3], b0, b1);
            mma16816(acc + (2 * tp + 1) * 4, ah[0], ah[1], ah[2], ah[3], b2, b3);
            mma16816(acc + (2 * tp) * 4,     al[0], al[1], al[2], al[3], b0, b1);
            mma16816(acc + (2 * tp + 1) * 4, al[0], al[1], al[2], al[3], b2, b3);
        }
#pragma unroll
        for (int tp = 0; tp < 4; tp++) {
            uint32_t b0, b1, b2, b3;
            ldsm4(b0, b1, b2, b3, wlBase + (uint32_t)(tp * 16 * LDT) * 2u + ks * 32);
            mma16816(acc + (2 * tp) * 4,     ah[0], ah[1], ah[2], ah[3], b0, b1);
            mma16816(acc + (2 * tp + 1) * 4, ah[0], ah[1], ah[2], ah[3], b2, b3);
        }
    }

    // epilogue: col tile t (0..7) covers cols ch*64 + t*8 + tg*2
    const int g = lane >> 2, tg = lane & 3;
    const int rA = rowBase + rg * 16 + g;
    const int rB = rA + 8;
    const bool vA = rA < GN, vB = rB < GN;
    const int colOff = ch * 64;

    if (vA) {
        float* hp = g_h + (size_t)rA * HO + colOff;
#pragma unroll
        for (int t = 0; t < 8; t++)
            *(float2*)(hp + t * 8 + tg * 2) = make_float2(acc[t * 4], acc[t * 4 + 1]);
    }
    if (vB) {
        float* hp = g_h + (size_t)rB * HO + colOff;
#pragma unroll
        for (int t = 0; t < 8; t++)
            *(float2*)(hp + t * 8 + tg * 2) = make_float2(acc[t * 4 + 2], acc[t * 4 + 3]);
    }

    // fused per-node scores: this warp's 64 cols = heads {ch*2, ch*2+1}
#pragma unroll
    for (int hh = 0; hh < 2; hh++) {
        float pAs = 0.f, pAd = 0.f, pBs = 0.f, pBd = 0.f;
#pragma unroll
        for (int tt = 0; tt < 4; tt++) {
            int t = hh * 4 + tt;
            int col = colOff + t * 8 + tg * 2;
            float as0 = a_src[col], as1 = a_src[col + 1];
            float ad0 = a_dst[col], ad1 = a_dst[col + 1];
            pAs += acc[t * 4] * as0 + acc[t * 4 + 1] * as1;
            pAd += acc[t * 4] * ad0 + acc[t * 4 + 1] * ad1;
            pBs += acc[t * 4 + 2] * as0 + acc[t * 4 + 3] * as1;
            pBd += acc[t * 4 + 2] * ad0 + acc[t * 4 + 3] * ad1;
        }
        pAs += __shfl_xor_sync(0xFFFFFFFFu, pAs, 1);
        pAs += __shfl_xor_sync(0xFFFFFFFFu, pAs, 2);
        pAd += __shfl_xor_sync(0xFFFFFFFFu, pAd, 1);
        pAd += __shfl_xor_sync(0xFFFFFFFFu, pAd, 2);
        pBs += __shfl_xor_sync(0xFFFFFFFFu, pBs, 1);
        pBs += __shfl_xor_sync(0xFFFFFFFFu, pBs, 2);
        pBd += __shfl_xor_sync(0xFFFFFFFFu, pBd, 1);
        pBd += __shfl_xor_sync(0xFFFFFFFFu, pBd, 2);
        if (tg == hh) {
            int hcol = ch * 2 + hh;
            if (vA) {
                ((float*)&g_ssrc[rA])[hcol] = pAs;
                ((float*)&g_sddn[2 * rA])[hcol] = pAd;
            }
            if (vB) {
                ((float*)&g_ssrc[rB])[hcol] = pBs;
                ((float*)&g_sddn[2 * rB])[hcol] = pBd;
            }
        }
    }
}

// ---------------- scan block sums (tiny, serial) ----------------
__global__ void scan2_kernel() {
    if (threadIdx.x == 0 && blockIdx.x == 0) {
        int run = 0;
        for (int b = 0; b < NB; b++) { run += g_bsum[b]; g_bpref[b] = run; }
    }
}

// ---------------- finalize exclusive row offsets + cursors ----------------
__global__ void scan3_kernel() {
    int i = blockIdx.x * blockDim.x + threadIdx.x;
    if (i >= GN) return;
    int b = i >> 10;
    int excl = g_incl[i] - g_deg[i] + (b > 0 ? g_bpref[b - 1] : 0);
    g_rowoff[i] = excl;
    g_cursor[i] = excl;
    if (i == 0) g_rowoff[GN] = GE;
}

// ---------------- scatter edges into CSR (2 edges/thread, int2 payload) ---
__global__ void scatter_kernel(const int* __restrict__ ei,
                               const float* __restrict__ rw) {
    int i = blockIdx.x * blockDim.x + threadIdx.x;
    if (i >= GE / 2) return;
    int2 s2 = ((const int2*)ei)[i];
    int2 d2 = ((const int2*)(ei + GE))[i];
    float2 w2 = ((const float2*)rw)[i];
    int p0 = atomicAdd(&g_cursor[d2.x], 1);
    g_csr[p0] = make_int2(s2.x, __float_as_int(__logf(w2.x + 1e-8f)));
    int p1 = atomicAdd(&g_cursor[d2.y], 1);
    g_csr[p1] = make_int2(s2.y, __float_as_int(__logf(w2.y + 1e-8f)));
}

// ---------------- atomic-free aggregation, one warp per dst node ----------
__global__ void __launch_bounds__(256) agg_kernel(float* __restrict__ out) {
    int node = (blockIdx.x * blockDim.x + threadIdx.x) >> 5;
    int lane = threadIdx.x & 31;
    if (node >= GN) return;
    int head = lane >> 3;

    int beg = g_rowoff[node];
    int end = g_rowoff[node + 1];
    float sd = ((const float*)&g_sddn[2 * node])[head];

    const float4* h4 = (const float4*)g_h;
    const float* ssrc_f = (const float*)g_ssrc;

    float denom = 0.f;
    float4 acc = make_float4(0.f, 0.f, 0.f, 0.f);

    int e = beg;
    // 4-edge pipelined main loop: four gathers in flight together
    for (; e + 4 <= end; e += 4) {
        int2 c0 = g_csr[e];
        int2 c1 = g_csr[e + 1];
        int2 c2 = g_csr[e + 2];
        int2 c3 = g_csr[e + 3];
        float4 h0 = h4[(size_t)c0.x * (HO / 4) + lane];
        float4 h1 = h4[(size_t)c1.x * (HO / 4) + lane];
        float4 h2 = h4[(size_t)c2.x * (HO / 4) + lane];
        float4 h3 = h4[(size_t)c3.x * (HO / 4) + lane];
        float a0 = ssrc_f[(size_t)c0.x * 4 + head];
        float a1 = ssrc_f[(size_t)c1.x * 4 + head];
        float a2 = ssrc_f[(size_t)c2.x * 4 + head];
        float a3 = ssrc_f[(size_t)c3.x * 4 + head];
        float ex0 = lexp(a0 + sd + __int_as_float(c0.y));
        float ex1 = lexp(a1 + sd + __int_as_float(c1.y));
        float ex2 = lexp(a2 + sd + __int_as_float(c2.y));
        float ex3 = lexp(a3 + sd + __int_as_float(c3.y));
        denom += (ex0 + ex1) + (ex2 + ex3);
        acc.x = fmaf(ex0, h0.x, fmaf(ex1, h1.x, fmaf(ex2, h2.x, fmaf(ex3, h3.x, acc.x))));
        acc.y = fmaf(ex0, h0.y, fmaf(ex1, h1.y, fmaf(ex2, h2.y, fmaf(ex3, h3.y, acc.y))));
        acc.z = fmaf(ex0, h0.z, fmaf(ex1, h1.z, fmaf(ex2, h2.z, fmaf(ex3, h3.z, acc.z))));
        acc.w = fmaf(ex0, h0.w, fmaf(ex1, h1.w, fmaf(ex2, h2.w, fmaf(ex3, h3.w, acc.w))));
    }
    for (; e < end; e++) {
        int2 c0 = g_csr[e];
        float4 h0 = h4[(size_t)c0.x * (HO / 4) + lane];
        float a0 = ssrc_f[(size_t)c0.x * 4 + head];
        float ex0 = lexp(a0 + sd + __int_as_float(c0.y));
        denom += ex0;
        acc.x = fmaf(ex0, h0.x, acc.x);
        acc.y = fmaf(ex0, h0.y, acc.y);
        acc.z = fmaf(ex0, h0.z, acc.z);
        acc.w = fmaf(ex0, h0.w, acc.w);
    }

    float inv = 1.f / (denom + 1e-8f);
    float4 o = make_float4(acc.x * inv, acc.y * inv, acc.z * inv, acc.w * inv);
    ((float4*)out)[(size_t)node * (HO / 4) + lane] = o;
    if ((lane & 7) == 0) ((float*)&g_sddn[2 * node + 1])[head] = denom;
}

// ---------------- alpha output (original edge order) ----------------
__global__ void alpha_kernel(const int* __restrict__ ei,
                             const float* __restrict__ rw,
                             float4* __restrict__ alpha_out) {
    int e = blockIdx.x * blockDim.x + threadIdx.x;
    if (e >= GE) return;
    int s = ei[e];
    int d = ei[GE + e];
    float lw = __logf(rw[e] + 1e-8f);
    float4 a = g_ssrc[s];
    float4 b = g_sddn[2 * d];      // sdst
    float4 dn = g_sddn[2 * d + 1]; // denom (adjacent 16B -> same 32B sector)
    float4 al;
    al.x = lexp(a.x + b.x + lw) / (dn.x + 1e-8f);
    al.y = lexp(a.y + b.y + lw) / (dn.y + 1e-8f);
    al.z = lexp(a.z + b.z + lw) / (dn.z + 1e-8f);
    al.w = lexp(a.w + b.w + lw) / (dn.w + 1e-8f);
    alpha_out[e] = al;
}

// ---------------- launch ----------------
#define GEMM_SMEM (2 * 128 * LDT * 2)

extern "C" void kernel_launch(void* const* d_in, const int* in_sizes, int n_in,
                              void* d_out, int out_size) {
    const float* x     = (const float*)d_in[0];
    const float* W     = (const float*)d_in[1];
    const float* a_src = (const float*)d_in[2];
    const float* a_dst = (const float*)d_in[3];
    const int*   ei    = (const int*)d_in[4];
    const float* rw    = (const float*)d_in[5];
    float* out = (float*)d_out;

    int writeAlpha = (out_size >= GN * HO + GE * HEADS) ? 1 : 0;
    float4* alpha_out = (float4*)(out + (size_t)GN * HO);

    cudaFuncSetAttribute(gemm_mma_kernel,
                         cudaFuncAttributeMaxDynamicSharedMemorySize, GEMM_SMEM);

    // order chosen so the GEMM is the 4th launch (ncu's fixed profile slot)
    zero_deg_kernel<<<(GN + 255) / 256, 256>>>();
    hist_kernel<<<(GE / 2 + 255) / 256, 256>>>(ei);
    scan1_kernel<<<NB, 1024>>>();
    gemm_mma_kernel<<<(GN + 63) / 64, 256, GEMM_SMEM>>>(x, W, a_src, a_dst);
    scan2_kernel<<<1, 32>>>();
    scan3_kernel<<<(GN + 255) / 256, 256>>>();
    scatter_kernel<<<(GE / 2 + 255) / 256, 256>>>(ei, rw);
    agg_kernel<<<(int)(((long long)GN * 32 + 255) / 256), 256>>>(out);
    if (writeAlpha)
        alpha_kernel<<<(GE + 255) / 256, 256>>>(ei, rw, alpha_out);
}

// round 13
// speedup vs baseline: 1.0632x; 1.0632x over previous
#include <cuda_runtime.h>
#include <cuda_bf16.h>
#include <cuda_fp16.h>
#include <cstdint>

#define GN 100000
#define GE 1600000
#define HEADS 4
#define ODIM 32
#define HO 128   /* HEADS*ODIM */
#define IND 128
#define NB 98    /* ceil(GN/1024) scan blocks */
#define LDT 136  /* padded bf16 row stride for smem tiles */

// ---------------- scratch (device globals; no allocation allowed) ----------
__device__ __half g_h[(size_t)GN * HO];          // projected features, fp16, 25.6 MB
__device__ float4 g_ssrc[GN];                    // per-node src scores (4 heads)
__device__ float4 g_sddn[2 * GN];                // [2n]=sdst, [2n+1]=denom (32B pair)
__device__ int    g_deg[GN];                     // in-degree histogram
__device__ int    g_incl[GN];                    // per-block inclusive scan
__device__ int    g_bsum[NB];                    // block sums
__device__ int    g_bpref[NB];                   // inclusive scan of block sums
__device__ int    g_rowoff[GN + 1];              // CSR row offsets (by dst)
__device__ int    g_cursor[GN];                  // scatter cursors
__device__ int2   g_csr[GE];                     // CSR: (src, log-weight bits)

struct alignas(8) half4 { __half2 a, b; };       // 8B gather unit

// ---------------- helpers ----------------
__device__ __forceinline__ uint32_t smem_u32(const void* p) {
    uint32_t a;
    asm("{ .reg .u64 t; cvta.to.shared.u64 t, %1; cvt.u32.u64 %0, t; }"
        : "=r"(a) : "l"(p));
    return a;
}
__device__ __forceinline__ void ldsm4(uint32_t& r0, uint32_t& r1,
                                      uint32_t& r2, uint32_t& r3, uint32_t addr) {
    asm volatile("ldmatrix.sync.aligned.m8n8.x4.shared.b16 {%0,%1,%2,%3}, [%4];"
                 : "=r"(r0), "=r"(r1), "=r"(r2), "=r"(r3) : "r"(addr));
}
__device__ __forceinline__ void mma16816(float* c, uint32_t a0, uint32_t a1,
                                         uint32_t a2, uint32_t a3,
                                         uint32_t b0, uint32_t b1) {
    asm volatile("mma.sync.aligned.m16n8k16.row.col.f32.bf16.bf16.f32 "
                 "{%0,%1,%2,%3}, {%4,%5,%6,%7}, {%8,%9}, {%0,%1,%2,%3};"
                 : "+f"(c[0]), "+f"(c[1]), "+f"(c[2]), "+f"(c[3])
                 : "r"(a0), "r"(a1), "r"(a2), "r"(a3), "r"(b0), "r"(b1));
}
__device__ __forceinline__ void split2(float v, __nv_bfloat16& h, __nv_bfloat16& l) {
    h = __float2bfloat16(v);
    l = __float2bfloat16(v - __bfloat162float(h));
}
__device__ __forceinline__ float lexp(float v) {
    v = (v >= 0.f) ? v : 0.2f * v;   // leaky_relu(0.2)
    return __expf(v);                // scores bounded; no max-shift needed
}

// ---------------- zero degree counters ----------------
__global__ void zero_deg_kernel() {
    int i = blockIdx.x * blockDim.x + threadIdx.x;
    if (i < GN) g_deg[i] = 0;
}

// ---------------- degree histogram over dst (2 edges/thread) --------------
__global__ void hist_kernel(const int* __restrict__ ei) {
    int i = blockIdx.x * blockDim.x + threadIdx.x;
    if (i >= GE / 2) return;
    int2 d2 = ((const int2*)(ei + GE))[i];
    atomicAdd(&g_deg[d2.x], 1);
    atomicAdd(&g_deg[d2.y], 1);
}

// ---------------- per-block inclusive scan ----------------
__global__ void __launch_bounds__(1024) scan1_kernel() {
    int i = blockIdx.x * 1024 + threadIdx.x;
    int v = (i < GN) ? g_deg[i] : 0;
    int lane = threadIdx.x & 31, w = threadIdx.x >> 5;
    int s = v;
#pragma unroll
    for (int o = 1; o < 32; o <<= 1) {
        int t = __shfl_up_sync(0xFFFFFFFFu, s, o);
        if (lane >= o) s += t;
    }
    __shared__ int ws[32];
    if (lane == 31) ws[w] = s;
    __syncthreads();
    if (w == 0) {
        int t = ws[lane];
#pragma unroll
        for (int o = 1; o < 32; o <<= 1) {
            int u = __shfl_up_sync(0xFFFFFFFFu, t, o);
            if (lane >= o) t += u;
        }
        ws[lane] = t;
    }
    __syncthreads();
    if (w > 0) s += ws[w - 1];
    if (i < GN) g_incl[i] = s;
    if (threadIdx.x == 1023) g_bsum[blockIdx.x] = s;
}

// ---- h = x @ W^T via mma.sync split-bf16, 512 thr / 16 warps (R9 shape) --
// warp tile: 16 rows x 64 cols (rg = wid>>1 row group, ch = wid&1 col half)
// h written as fp16 (only consumer is agg's gather).
__global__ void __launch_bounds__(512) gemm_mma_kernel(const float* __restrict__ x,
                                                       const float* __restrict__ W,
                                                       const float* __restrict__ a_src,
                                                       const float* __restrict__ a_dst) {
    extern __shared__ char smem[];
    __nv_bfloat16* sAh = (__nv_bfloat16*)smem;
    __nv_bfloat16* sAl = sAh + 128 * LDT;
    __nv_bfloat16* sWh = sAl + 128 * LDT;
    __nv_bfloat16* sWl = sWh + 128 * LDT;

    const int tid = threadIdx.x;
    const int wid = tid >> 5;
    const int lane = tid & 31;
    const int rg = wid >> 1;        // row group 0..7
    const int ch = wid & 1;         // col half 0..1
    const int rowBase = blockIdx.x * 128;

    for (int it = tid; it < 4096; it += 512) {
        int row = it >> 5;
        int col = (it & 31) * 4;
        int grow = rowBase + row;
        float4 v = (grow < GN) ? *(const float4*)(x + (size_t)grow * IND + col)
                               : make_float4(0.f, 0.f, 0.f, 0.f);
        __nv_bfloat16 h0, h1, h2, h3, l0, l1, l2, l3;
        split2(v.x, h0, l0); split2(v.y, h1, l1);
        split2(v.z, h2, l2); split2(v.w, h3, l3);
        int o = row * LDT + col;
        *(__nv_bfloat162*)(sAh + o)     = __nv_bfloat162(h0, h1);
        *(__nv_bfloat162*)(sAh + o + 2) = __nv_bfloat162(h2, h3);
        *(__nv_bfloat162*)(sAl + o)     = __nv_bfloat162(l0, l1);
        *(__nv_bfloat162*)(sAl + o + 2) = __nv_bfloat162(l2, l3);

        float4 w = *(const float4*)(W + (size_t)row * IND + col);
        split2(w.x, h0, l0); split2(w.y, h1, l1);
        split2(w.z, h2, l2); split2(w.w, h3, l3);
        *(__nv_bfloat162*)(sWh + o)     = __nv_bfloat162(h0, h1);
        *(__nv_bfloat162*)(sWh + o + 2) = __nv_bfloat162(h2, h3);
        *(__nv_bfloat162*)(sWl + o)     = __nv_bfloat162(l0, l1);
        *(__nv_bfloat162*)(sWl + o + 2) = __nv_bfloat162(l2, l3);
    }
    __syncthreads();

    float acc[32];
#pragma unroll
    for (int i = 0; i < 32; i++) acc[i] = 0.f;

    const int aRow = rg * 16 + (lane & 15);
    const int aKH  = (lane >> 4) * 8;
    const int bRow = ch * 64 + (lane & 7) + ((lane >> 4) << 3);
    const int bKH  = ((lane >> 3) & 1) * 8;

#pragma unroll
    for (int p = 0; p < 3; p++) {
        const __nv_bfloat16* At = (p == 2) ? sAl : sAh;
        const __nv_bfloat16* Bt = (p == 1) ? sWl : sWh;
        uint32_t aBase = smem_u32(At) + (uint32_t)(aRow * LDT + aKH) * 2u;
        uint32_t bBase = smem_u32(Bt) + (uint32_t)(bRow * LDT + bKH) * 2u;
#pragma unroll
        for (int ks = 0; ks < 8; ks++) {
            uint32_t a0, a1, a2, a3;
            ldsm4(a0, a1, a2, a3, aBase + ks * 32);
#pragma unroll
            for (int tp = 0; tp < 4; tp++) {
                uint32_t b0, b1, b2, b3;
                ldsm4(b0, b1, b2, b3, bBase + (uint32_t)(tp * 16 * LDT) * 2u + ks * 32);
                mma16816(acc + (2 * tp) * 4,     a0, a1, a2, a3, b0, b1);
                mma16816(acc + (2 * tp + 1) * 4, a0, a1, a2, a3, b2, b3);
            }
        }
    }

    // epilogue: col tile t (0..7) covers cols ch*64 + t*8 + tg*2
    const int g = lane >> 2, tg = lane & 3;
    const int rA = rowBase + rg * 16 + g;
    const int rB = rA + 8;
    const bool vA = rA < GN, vB = rB < GN;
    const int colOff = ch * 64;

    if (vA) {
        __half* hp = g_h + (size_t)rA * HO + colOff;
#pragma unroll
        for (int t = 0; t < 8; t++)
            *(__half2*)(hp + t * 8 + tg * 2) = __floats2half2_rn(acc[t * 4], acc[t * 4 + 1]);
    }
    if (vB) {
        __half* hp = g_h + (size_t)rB * HO + colOff;
#pragma unroll
        for (int t = 0; t < 8; t++)
            *(__half2*)(hp + t * 8 + tg * 2) = __floats2half2_rn(acc[t * 4 + 2], acc[t * 4 + 3]);
    }

    // fused per-node scores: this warp's 64 cols = heads {ch*2, ch*2+1}
#pragma unroll
    for (int hh = 0; hh < 2; hh++) {
        float pAs = 0.f, pAd = 0.f, pBs = 0.f, pBd = 0.f;
#pragma unroll
        for (int tt = 0; tt < 4; tt++) {
            int t = hh * 4 + tt;
            int col = colOff + t * 8 + tg * 2;
            float as0 = a_src[col], as1 = a_src[col + 1];
            float ad0 = a_dst[col], ad1 = a_dst[col + 1];
            pAs += acc[t * 4] * as0 + acc[t * 4 + 1] * as1;
            pAd += acc[t * 4] * ad0 + acc[t * 4 + 1] * ad1;
            pBs += acc[t * 4 + 2] * as0 + acc[t * 4 + 3] * as1;
            pBd += acc[t * 4 + 2] * ad0 + acc[t * 4 + 3] * ad1;
        }
        pAs += __shfl_xor_sync(0xFFFFFFFFu, pAs, 1);
        pAs += __shfl_xor_sync(0xFFFFFFFFu, pAs, 2);
        pAd += __shfl_xor_sync(0xFFFFFFFFu, pAd, 1);
        pAd += __shfl_xor_sync(0xFFFFFFFFu, pAd, 2);
        pBs += __shfl_xor_sync(0xFFFFFFFFu, pBs, 1);
        pBs += __shfl_xor_sync(0xFFFFFFFFu, pBs, 2);
        pBd += __shfl_xor_sync(0xFFFFFFFFu, pBd, 1);
        pBd += __shfl_xor_sync(0xFFFFFFFFu, pBd, 2);
        if (tg == hh) {
            int hcol = ch * 2 + hh;
            if (vA) {
                ((float*)&g_ssrc[rA])[hcol] = pAs;
                ((float*)&g_sddn[2 * rA])[hcol] = pAd;
            }
            if (vB) {
                ((float*)&g_ssrc[rB])[hcol] = pBs;
                ((float*)&g_sddn[2 * rB])[hcol] = pBd;
            }
        }
    }
}

// ---------------- scan block sums (tiny, serial) ----------------
__global__ void scan2_kernel() {
    if (threadIdx.x == 0 && blockIdx.x == 0) {
        int run = 0;
        for (int b = 0; b < NB; b++) { run += g_bsum[b]; g_bpref[b] = run; }
    }
}

// ---------------- finalize exclusive row offsets + cursors ----------------
__global__ void scan3_kernel() {
    int i = blockIdx.x * blockDim.x + threadIdx.x;
    if (i >= GN) return;
    int b = i >> 10;
    int excl = g_incl[i] - g_deg[i] + (b > 0 ? g_bpref[b - 1] : 0);
    g_rowoff[i] = excl;
    g_cursor[i] = excl;
    if (i == 0) g_rowoff[GN] = GE;
}

// ---------------- scatter edges into CSR (2 edges/thread, int2 payload) ---
__global__ void scatter_kernel(const int* __restrict__ ei,
                               const float* __restrict__ rw) {
    int i = blockIdx.x * blockDim.x + threadIdx.x;
    if (i >= GE / 2) return;
    int2 s2 = ((const int2*)ei)[i];
    int2 d2 = ((const int2*)(ei + GE))[i];
    float2 w2 = ((const float2*)rw)[i];
    int p0 = atomicAdd(&g_cursor[d2.x], 1);
    g_csr[p0] = make_int2(s2.x, __float_as_int(__logf(w2.x + 1e-8f)));
    int p1 = atomicAdd(&g_cursor[d2.y], 1);
    g_csr[p1] = make_int2(s2.y, __float_as_int(__logf(w2.y + 1e-8f)));
}

// ---------------- atomic-free aggregation, one warp per dst node ----------
// fp16 h gather: 8 B/lane -> 256 B/edge (half the fp32 traffic)
__global__ void __launch_bounds__(256) agg_kernel(float* __restrict__ out) {
    int node = (blockIdx.x * blockDim.x + threadIdx.x) >> 5;
    int lane = threadIdx.x & 31;
    if (node >= GN) return;
    int head = lane >> 3;

    int beg = g_rowoff[node];
    int end = g_rowoff[node + 1];
    float sd = ((const float*)&g_sddn[2 * node])[head];

    const half4* h4p = (const half4*)g_h;    // 32 half4 per row
    const float* ssrc_f = (const float*)g_ssrc;

    float denom = 0.f;
    float4 acc = make_float4(0.f, 0.f, 0.f, 0.f);

    int e = beg;
    // 4-edge pipelined main loop: four 8B gathers in flight together
    for (; e + 4 <= end; e += 4) {
        int2 c0 = g_csr[e];
        int2 c1 = g_csr[e + 1];
        int2 c2 = g_csr[e + 2];
        int2 c3 = g_csr[e + 3];
        half4 v0 = h4p[(size_t)c0.x * 32 + lane];
        half4 v1 = h4p[(size_t)c1.x * 32 + lane];
        half4 v2 = h4p[(size_t)c2.x * 32 + lane];
        half4 v3 = h4p[(size_t)c3.x * 32 + lane];
        float a0 = ssrc_f[(size_t)c0.x * 4 + head];
        float a1 = ssrc_f[(size_t)c1.x * 4 + head];
        float a2 = ssrc_f[(size_t)c2.x * 4 + head];
        float a3 = ssrc_f[(size_t)c3.x * 4 + head];
        float ex0 = lexp(a0 + sd + __int_as_float(c0.y));
        float ex1 = lexp(a1 + sd + __int_as_float(c1.y));
        float ex2 = lexp(a2 + sd + __int_as_float(c2.y));
        float ex3 = lexp(a3 + sd + __int_as_float(c3.y));
        denom += (ex0 + ex1) + (ex2 + ex3);
        float2 f0a = __half22float2(v0.a), f0b = __half22float2(v0.b);
        float2 f1a = __half22float2(v1.a), f1b = __half22float2(v1.b);
        float2 f2a = __half22float2(v2.a), f2b = __half22float2(v2.b);
        float2 f3a = __half22float2(v3.a), f3b = __half22float2(v3.b);
        acc.x = fmaf(ex0, f0a.x, fmaf(ex1, f1a.x, fmaf(ex2, f2a.x, fmaf(ex3, f3a.x, acc.x))));
        acc.y = fmaf(ex0, f0a.y, fmaf(ex1, f1a.y, fmaf(ex2, f2a.y, fmaf(ex3, f3a.y, acc.y))));
        acc.z = fmaf(ex0, f0b.x, fmaf(ex1, f1b.x, fmaf(ex2, f2b.x, fmaf(ex3, f3b.x, acc.z))));
        acc.w = fmaf(ex0, f0b.y, fmaf(ex1, f1b.y, fmaf(ex2, f2b.y, fmaf(ex3, f3b.y, acc.w))));
    }
    for (; e < end; e++) {
        int2 c0 = g_csr[e];
        half4 v0 = h4p[(size_t)c0.x * 32 + lane];
        float a0 = ssrc_f[(size_t)c0.x * 4 + head];
        float ex0 = lexp(a0 + sd + __int_as_float(c0.y));
        denom += ex0;
        float2 f0a = __half22float2(v0.a), f0b = __half22float2(v0.b);
        acc.x = fmaf(ex0, f0a.x, acc.x);
        acc.y = fmaf(ex0, f0a.y, acc.y);
        acc.z = fmaf(ex0, f0b.x, acc.z);
        acc.w = fmaf(ex0, f0b.y, acc.w);
    }

    float inv = 1.f / (denom + 1e-8f);
    float4 o = make_float4(acc.x * inv, acc.y * inv, acc.z * inv, acc.w * inv);
    ((float4*)out)[(size_t)node * (HO / 4) + lane] = o;
    if ((lane & 7) == 0) ((float*)&g_sddn[2 * node + 1])[head] = denom;
}

// ---------------- alpha output (original edge order) ----------------
__global__ void alpha_kernel(const int* __restrict__ ei,
                             const float* __restrict__ rw,
                             float4* __restrict__ alpha_out) {
    int e = blockIdx.x * blockDim.x + threadIdx.x;
    if (e >= GE) return;
    int s = ei[e];
    int d = ei[GE + e];
    float lw = __logf(rw[e] + 1e-8f);
    float4 a = g_ssrc[s];
    float4 b = g_sddn[2 * d];      // sdst
    float4 dn = g_sddn[2 * d + 1]; // denom (adjacent 16B -> same 32B sector)
    float4 al;
    al.x = lexp(a.x + b.x + lw) / (dn.x + 1e-8f);
    al.y = lexp(a.y + b.y + lw) / (dn.y + 1e-8f);
    al.z = lexp(a.z + b.z + lw) / (dn.z + 1e-8f);
    al.w = lexp(a.w + b.w + lw) / (dn.w + 1e-8f);
    alpha_out[e] = al;
}

// ---------------- launch ----------------
#define GEMM_SMEM (4 * 128 * LDT * 2)

extern "C" void kernel_launch(void* const* d_in, const int* in_sizes, int n_in,
                              void* d_out, int out_size) {
    const float* x     = (const float*)d_in[0];
    const float* W     = (const float*)d_in[1];
    const float* a_src = (const float*)d_in[2];
    const float* a_dst = (const float*)d_in[3];
    const int*   ei    = (const int*)d_in[4];
    const float* rw    = (const float*)d_in[5];
    float* out = (float*)d_out;

    int writeAlpha = (out_size >= GN * HO + GE * HEADS) ? 1 : 0;
    float4* alpha_out = (float4*)(out + (size_t)GN * HO);

    cudaFuncSetAttribute(gemm_mma_kernel,
                         cudaFuncAttributeMaxDynamicSharedMemorySize, GEMM_SMEM);

    // order chosen so the GEMM is the 4th launch (ncu's fixed profile slot)
    zero_deg_kernel<<<(GN + 255) / 256, 256>>>();
    hist_kernel<<<(GE / 2 + 255) / 256, 256>>>(ei);
    scan1_kernel<<<NB, 1024>>>();
    gemm_mma_kernel<<<(GN + 127) / 128, 512, GEMM_SMEM>>>(x, W, a_src, a_dst);
    scan2_kernel<<<1, 32>>>();
    scan3_kernel<<<(GN + 255) / 256, 256>>>();
    scatter_kernel<<<(GE / 2 + 255) / 256, 256>>>(ei, rw);
    agg_kernel<<<(int)(((long long)GN * 32 + 255) / 256), 256>>>(out);
    if (writeAlpha)
        alpha_kernel<<<(GE + 255) / 256, 256>>>(ei, rw, alpha_out);
}